// round 6
// baseline (speedup 1.0000x reference)
#include <cuda_runtime.h>
#include <cstddef>

#define B_    4096
#define T_    128
#define NL_   256
#define NS_   64
#define NO_   32
#define V_    64

#define ROWS_ 32      // batch rows per CTA
#define NTH_  512     // 16 warps
#define KB_   32      // K per W1 chunk (row = 32 floats = 128 B, swizzled in 8B slots)
#define NCH_  8       // chunks per step
#define XP_   260     // latent tile pitch (floats): 1040B rows, 16B aligned

typedef unsigned long long u64;

__device__ __forceinline__ u64 ffma2(u64 a, u64 b, u64 c) {
    u64 d;
    asm("fma.rn.f32x2 %0, %1, %2, %3;" : "=l"(d) : "l"(a), "l"(b), "l"(c));
    return d;
}

__device__ __forceinline__ void cp8(float* dst_smem, const float* src) {
    unsigned int d = (unsigned int)__cvta_generic_to_shared(dst_smem);
    asm volatile("cp.async.ca.shared.global [%0], [%1], 8;" :: "r"(d), "l"(src) : "memory");
}
__device__ __forceinline__ void cp16(float* dst_smem, const float* src) {
    unsigned int d = (unsigned int)__cvta_generic_to_shared(dst_smem);
    asm volatile("cp.async.cg.shared.global [%0], [%1], 16;" :: "r"(d), "l"(src) : "memory");
}

// Stage one 256x32 chunk of W1[s], XOR-swizzled at 8B granule:
// element (j, kp) -> ws[j*32 + 2*(kp ^ (j&15))].  4096 granules, 8 per thread.
__device__ __forceinline__ void stage_chunk(const float* W1s, int kb, float* ws, int tid) {
    #pragma unroll
    for (int q = 0; q < 8; ++q) {
        int g  = tid + NTH_ * q;        // 0..4095
        int j  = g >> 4;                // row 0..255
        int kp = g & 15;                // 8B slot 0..15
        cp8(ws + j * KB_ + (((kp ^ (j & 15))) << 1),
            W1s + (size_t)j * NL_ + kb + 2 * kp);
    }
    asm volatile("cp.async.commit_group;" ::: "memory");
}

// Dynamic smem (floats):
//   xA[32*260], xB[32*260]   latent ping/pong
//   wsA[256*32], wsB[256*32] W1 chunk double buffer (swizzled)
//   ws2[32*260]              W2 stage (plain, pitch 260)
//   yb[32*64]                scatter rows
//   seq[128] (int)
__global__ void __launch_bounds__(NTH_, 1)
lalr_persistent_kernel(const float* __restrict__ latent0,
                       const float* __restrict__ W1,
                       const float* __restrict__ b1,
                       const float* __restrict__ W2,
                       const float* __restrict__ b2,
                       const int*   __restrict__ state_seq,
                       const int*   __restrict__ out_idx,
                       float*       __restrict__ out)
{
    extern __shared__ float sm[];
    float* xA  = sm;
    float* xB  = xA  + ROWS_ * XP_;
    float* wsA = xB  + ROWS_ * XP_;
    float* wsB = wsA + 256 * KB_;
    float* ws2 = wsB + 256 * KB_;
    float* yb  = ws2 + NO_ * XP_;
    int*   seq = (int*)(yb + ROWS_ * V_);

    const int tid  = threadIdx.x;
    const int w    = tid >> 5;
    const int lane = tid & 31;
    const int r0   = blockIdx.x * ROWS_;

    const int rb  = (w >> 2) * 8;      // phase-1 rows rb..rb+7 (4 groups)
    const int jb  = (w & 3) * 64;      // phase-1 col group of 64 (2 sub-cols)
    const int rw2 = w * 2;             // phase-2 rows

    if (tid < T_) seq[tid] = state_seq[tid];

    for (int i = tid; i < ROWS_ * NL_; i += NTH_) {
        int r = i >> 8;
        int k = i & (NL_ - 1);
        xA[r * XP_ + k] = latent0[(size_t)(r0 + r) * NL_ + k];
    }

    // Prologue: chunk 0 of step 0.
    stage_chunk(W1 + (size_t)state_seq[0] * (NL_ * NL_), 0, wsA, tid);
    __syncthreads();

    float* xcur = xA;
    float* xnew = xB;

    for (int t = 0; t < T_; ++t) {
        const int s = seq[t];
        const float* W1s = W1 + (size_t)s * (NL_ * NL_);

        // Stage W2[s] into ws2 (completion forced by the c=0 wait below).
        #pragma unroll
        for (int q = 0; q < 4; ++q) {
            int idx4 = tid + q * NTH_;             // 0..2047
            int o    = idx4 >> 6;
            int k4   = (idx4 & 63) << 2;
            cp16(ws2 + o * XP_ + k4, W2 + ((size_t)s * NO_ + o) * NL_ + k4);
        }
        asm volatile("cp.async.commit_group;" ::: "memory");

        // ------------- Phase 1: x_new = tanh(x @ W1[s]^T + b1[s]) -------------
        u64 acc[8][2];
        #pragma unroll
        for (int i = 0; i < 8; ++i) { acc[i][0] = 0ull; acc[i][1] = 0ull; }

        for (int c = 0; c < NCH_; ++c) {
            {   // prefetch next chunk (c==NCH_-1 -> next step's chunk 0 into wsA)
                const float* Wn; int kbn;
                int cn = c + 1;
                if (cn < NCH_) { Wn = W1s; kbn = cn * KB_; }
                else {
                    int sn = (t < T_ - 1) ? seq[t + 1] : s;
                    Wn = W1 + (size_t)sn * (NL_ * NL_); kbn = 0;
                }
                stage_chunk(Wn, kbn, (cn & 1) ? wsB : wsA, tid);
            }
            asm volatile("cp.async.wait_group 1;" ::: "memory");
            __syncthreads();

            const float* ws = (c & 1) ? wsB : wsA;
            const int kb = c * KB_;
            const int lx = lane & 15;

            #pragma unroll 4
            for (int m4 = 0; m4 < KB_ / 4; ++m4) {
                // W loads: conflict-free swizzled LDS.64
                const int s0 = ((2 * m4)     ^ lx) << 1;
                const int s1 = ((2 * m4 + 1) ^ lx) << 1;
                const float* w0 = ws + (jb + lane) * KB_;
                const float* w1 = ws + (jb + lane + 32) * KB_;
                u64 w0l = *(const u64*)(w0 + s0);
                u64 w0h = *(const u64*)(w0 + s1);
                u64 w1l = *(const u64*)(w1 + s0);
                u64 w1h = *(const u64*)(w1 + s1);

                #pragma unroll
                for (int h = 0; h < 2; ++h) {
                    ulonglong2 xq[4];
                    #pragma unroll
                    for (int i = 0; i < 4; ++i)
                        xq[i] = *(const ulonglong2*)(xcur + (rb + 4 * h + i) * XP_ + kb + 4 * m4);
                    #pragma unroll
                    for (int i = 0; i < 4; ++i) {
                        int r = 4 * h + i;
                        acc[r][0] = ffma2(xq[i].x, w0l, acc[r][0]);
                        acc[r][0] = ffma2(xq[i].y, w0h, acc[r][0]);
                        acc[r][1] = ffma2(xq[i].x, w1l, acc[r][1]);
                        acc[r][1] = ffma2(xq[i].y, w1h, acc[r][1]);
                    }
                }
            }
            __syncthreads();   // all done with buf[c&1] before next restage
        }

        // bias + tanh -> xnew
        #pragma unroll
        for (int v = 0; v < 2; ++v) {
            int j = jb + lane + 32 * v;
            float bb = __ldg(b1 + s * NL_ + j);
            #pragma unroll
            for (int i = 0; i < 8; ++i) {
                float lo = __uint_as_float((unsigned)acc[i][v]);
                float hi = __uint_as_float((unsigned)(acc[i][v] >> 32));
                xnew[(rb + i) * XP_ + j] = tanhf(lo + hi + bb);
            }
        }
        __syncthreads();       // xnew visible (W2 already resident since c=0 wait)

        // ------------- Phase 2: probs = softmax(x_new @ W2[s]^T + b2[s]) -------
        u64 a2[2] = {0ull, 0ull};
        {
            const ulonglong2* wr = (const ulonglong2*)(ws2 + lane * XP_);
            const ulonglong2* x0 = (const ulonglong2*)(xnew + (rw2 + 0) * XP_);
            const ulonglong2* x1 = (const ulonglong2*)(xnew + (rw2 + 1) * XP_);
            #pragma unroll 8
            for (int k4 = 0; k4 < NL_ / 4; ++k4) {
                ulonglong2 wv = wr[k4];
                ulonglong2 v0 = x0[k4];
                a2[0] = ffma2(wv.x, v0.x, a2[0]); a2[0] = ffma2(wv.y, v0.y, a2[0]);
                ulonglong2 v1 = x1[k4];
                a2[1] = ffma2(wv.x, v1.x, a2[1]); a2[1] = ffma2(wv.y, v1.y, a2[1]);
            }
        }

        const float bb2  = __ldg(b2 + s * NO_ + lane);
        const int   idxv = __ldg(out_idx + s * NO_ + lane);
        const unsigned mm = __match_any_sync(0xffffffffu, idxv);
        const bool winner = (lane == (31 - __clz(mm)));

        #pragma unroll
        for (int i = 0; i < 2; ++i) {
            float lo = __uint_as_float((unsigned)a2[i]);
            float hi = __uint_as_float((unsigned)(a2[i] >> 32));
            float v  = lo + hi + bb2;

            float m = v;
            #pragma unroll
            for (int d = 16; d > 0; d >>= 1)
                m = fmaxf(m, __shfl_xor_sync(0xffffffffu, m, d));
            float e = expf(v - m);
            float ssum = e;
            #pragma unroll
            for (int d = 16; d > 0; d >>= 1)
                ssum += __shfl_xor_sync(0xffffffffu, ssum, d);
            float p = e / ssum;

            float* yrow = yb + (rw2 + i) * V_;
            yrow[lane]      = 0.0f;
            yrow[lane + 32] = 0.0f;
            __syncwarp();
            if (winner) yrow[idxv] = p;
            __syncwarp();
            float2 o2 = *(const float2*)(yrow + lane * 2);
            *(float2*)(out + ((size_t)(r0 + rw2 + i) * T_ + t) * V_ + lane * 2) = o2;
        }
        __syncthreads();   // phase2 done with ws2/xnew before next step restages

        float* tmp = xcur; xcur = xnew; xnew = tmp;
    }
}

extern "C" void kernel_launch(void* const* d_in, const int* in_sizes, int n_in,
                              void* d_out, int out_size)
{
    const float* latent0   = (const float*)d_in[0];
    const float* W1        = (const float*)d_in[1];
    const float* b1        = (const float*)d_in[2];
    const float* W2        = (const float*)d_in[3];
    const float* b2        = (const float*)d_in[4];
    const int*   state_seq = (const int*)  d_in[5];
    const int*   out_idx   = (const int*)  d_in[6];
    float*       out       = (float*)      d_out;

    const int smem_bytes = (2 * ROWS_ * XP_ + 2 * 256 * KB_ + NO_ * XP_ + ROWS_ * V_)
                           * (int)sizeof(float) + T_ * (int)sizeof(int);   // 174,592 B

    cudaFuncSetAttribute(lalr_persistent_kernel,
                         cudaFuncAttributeMaxDynamicSharedMemorySize, smem_bytes);

    lalr_persistent_kernel<<<B_ / ROWS_, NTH_, smem_bytes>>>(
        latent0, W1, b1, W2, b2, state_seq, out_idx, out);
}

// round 8
// speedup vs baseline: 2.2048x; 2.2048x over previous
#include <cuda_runtime.h>
#include <cuda_bf16.h>
#include <cstdint>
#include <cstddef>

#define B_    4096
#define T_    128
#define NL_   256
#define NS_   64
#define NO_   32
#define V_    64
#define ROWS_ 32
#define GRID_ 128
#define NTH_  256

// smem byte offsets
#define OFF_SEQ   0          // 128 ints
#define OFF_SB1   512        // 256 f32
#define OFF_SB2   1536       // 32 f32
#define OFF_SIDX  1664       // 32 int
#define OFF_YLOG  1792       // 32*36 f32 = 4608
#define OFF_YB    6400       // 32*68 f32 = 8704
#define OFF_XH    15360      // 32*528B
#define OFF_XL    32256
#define OFF_W2H   49152      // 32*528B
#define OFF_W2L   66048
#define OFF_W1    82944      // 3 bufs * 40960
#define SMEM_TOTAL 205824

#define XPB   528            // x / W2 plane pitch (bytes): 33 granules, conflict-free
#define W1PB  80             // W1 chunk plane pitch (bytes): 5 granules, conflict-free
#define W1PLANE 20480
#define W1BUF   40960

__device__ __nv_bfloat16 g_W1h[(size_t)NS_ * NL_ * NL_];
__device__ __nv_bfloat16 g_W1l[(size_t)NS_ * NL_ * NL_];
__device__ __nv_bfloat16 g_W2h[(size_t)NS_ * NO_ * NL_];
__device__ __nv_bfloat16 g_W2l[(size_t)NS_ * NO_ * NL_];

__device__ __forceinline__ void cp16g(uint32_t dst, const void* src) {
    asm volatile("cp.async.cg.shared.global [%0], [%1], 16;" :: "r"(dst), "l"(src) : "memory");
}
#define CPCOMMIT() asm volatile("cp.async.commit_group;" ::: "memory")

__device__ __forceinline__ void ldm4(uint32_t a, uint32_t& r0, uint32_t& r1, uint32_t& r2, uint32_t& r3) {
    asm volatile("ldmatrix.sync.aligned.m8n8.x4.shared.b16 {%0,%1,%2,%3}, [%4];"
                 : "=r"(r0), "=r"(r1), "=r"(r2), "=r"(r3) : "r"(a));
}
__device__ __forceinline__ void ldm2(uint32_t a, uint32_t& r0, uint32_t& r1) {
    asm volatile("ldmatrix.sync.aligned.m8n8.x2.shared.b16 {%0,%1}, [%2];"
                 : "=r"(r0), "=r"(r1) : "r"(a));
}
__device__ __forceinline__ void mma16816(float* d, const uint32_t* a, uint32_t b0, uint32_t b1) {
    asm volatile("mma.sync.aligned.m16n8k16.row.col.f32.bf16.bf16.f32 "
                 "{%0,%1,%2,%3}, {%4,%5,%6,%7}, {%8,%9}, {%0,%1,%2,%3};"
                 : "+f"(d[0]), "+f"(d[1]), "+f"(d[2]), "+f"(d[3])
                 : "r"(a[0]), "r"(a[1]), "r"(a[2]), "r"(a[3]), "r"(b0), "r"(b1));
}
__device__ __forceinline__ float tanh_acc(float x) {
    float xc = fminf(fmaxf(x, -15.f), 15.f);
    float e = __expf(2.f * xc);
    return __fdividef(e - 1.f, e + 1.f);
}
__device__ __forceinline__ void pack2(float f0, float f1, uint32_t& hp, uint32_t& lp) {
    asm("cvt.rn.bf16x2.f32 %0, %1, %2;" : "=r"(hp) : "f"(f1), "f"(f0));
    float h0 = __uint_as_float(hp << 16);
    float h1 = __uint_as_float(hp & 0xffff0000u);
    asm("cvt.rn.bf16x2.f32 %0, %1, %2;" : "=r"(lp) : "f"(f1 - h1), "f"(f0 - h0));
}

// Stage one [256n x 32k] chunk (hi+lo) of W1[s] into buffer b. 2048 cp16.
__device__ __forceinline__ void stage_w1(uint32_t s0, int b, int s, int ck, int tid) {
    uint32_t base = s0 + OFF_W1 + (uint32_t)b * W1BUF;
    const __nv_bfloat16* srch = g_W1h + (size_t)s * NL_ * NL_ + ck * 32;
    const __nv_bfloat16* srcl = g_W1l + (size_t)s * NL_ * NL_ + ck * 32;
    #pragma unroll
    for (int q = 0; q < 8; ++q) {
        int g = tid + NTH_ * q;          // 0..2047
        int pl = g >> 10;
        int rem = g & 1023;
        int n = rem >> 2, slot = rem & 3;
        uint32_t d = base + (uint32_t)(pl * W1PLANE + n * W1PB + slot * 16);
        const __nv_bfloat16* p = (pl ? srcl : srch) + (size_t)n * NL_ + slot * 8;
        cp16g(d, p);
    }
}
// Stage W2[s] hi+lo (32n x 256k, pitch XPB). 2048 cp16.
__device__ __forceinline__ void stage_w2(uint32_t s0, int s, int tid) {
    #pragma unroll
    for (int q = 0; q < 8; ++q) {
        int g = tid + NTH_ * q;
        int pl = g >> 10;
        int rem = g & 1023;
        int n = rem >> 5, slot = rem & 31;
        uint32_t d = s0 + (uint32_t)((pl ? OFF_W2L : OFF_W2H) + n * XPB + slot * 16);
        const __nv_bfloat16* p = (pl ? g_W2l : g_W2h) + (size_t)(s * NO_ + n) * NL_ + slot * 8;
        cp16g(d, p);
    }
}

__global__ void cvt_kernel(const float* __restrict__ W1, const float* __restrict__ W2) {
    size_t i = (size_t)blockIdx.x * blockDim.x + threadIdx.x;
    if (i < (size_t)NS_ * NL_ * NL_) {
        float x = W1[i];
        __nv_bfloat16 h = __float2bfloat16(x);
        g_W1h[i] = h;
        g_W1l[i] = __float2bfloat16(x - __bfloat162float(h));
    }
    if (i < (size_t)NS_ * NO_ * NL_) {
        float x = W2[i];
        __nv_bfloat16 h = __float2bfloat16(x);
        g_W2h[i] = h;
        g_W2l[i] = __float2bfloat16(x - __bfloat162float(h));
    }
}

__global__ __launch_bounds__(NTH_, 1)
void lalr_hmma_kernel(const float* __restrict__ latent0,
                      const float* __restrict__ b1,
                      const float* __restrict__ b2,
                      const int*   __restrict__ state_seq,
                      const int*   __restrict__ out_idx,
                      float*       __restrict__ out)
{
    extern __shared__ char smc[];
    const uint32_t s0 = (uint32_t)__cvta_generic_to_shared(smc);
    const int tid  = threadIdx.x;
    const int w    = tid >> 5;
    const int lane = tid & 31;
    const int r0   = blockIdx.x * ROWS_;

    int*   seq  = (int*)(smc + OFF_SEQ);
    float* sb1  = (float*)(smc + OFF_SB1);
    float* sb2  = (float*)(smc + OFF_SB2);
    int*   sidx = (int*)(smc + OFF_SIDX);
    float* ylog = (float*)(smc + OFF_YLOG);   // pitch 36 floats
    float* yb   = (float*)(smc + OFF_YB);     // pitch 68 floats

    // warp tiling
    const int mrow  = (w & 1) * 16;           // phase-1 row tile
    const int ncol0 = (w >> 1) * 64;          // phase-1 col group (8 n-tiles)
    const int mrow2 = (w & 1) * 16;           // phase-2 row tile
    const int nb2   = (w >> 1) * 8;           // phase-2 n-tile

    // ldmatrix lane addressing precompute
    const int a_row = (lane & 7) + ((lane >> 3) & 1) * 8;     // + mrow
    const int a_kof = (lane >> 4) * 8;                        // + k base
    const int b_row = (lane & 7) + ((lane >> 4) & 1) * 8;     // + nbase
    const int b_kof = ((lane >> 3) & 1) * 8;                  // + k base

    if (tid < T_) seq[tid] = state_seq[tid];

    // initial latent -> XH/XL planes (bf16 hi/lo)
    {
        int r = tid >> 3;
        int cb = (tid & 7) * 32;
        const float2* src = (const float2*)(latent0 + (size_t)(r0 + r) * NL_ + cb);
        #pragma unroll
        for (int i = 0; i < 16; ++i) {
            float2 f = src[i];
            uint32_t hp, lp;
            pack2(f.x, f.y, hp, lp);
            *(uint32_t*)(smc + OFF_XH + r * XPB + (cb + 2 * i) * 2) = hp;
            *(uint32_t*)(smc + OFF_XL + r * XPB + (cb + 2 * i) * 2) = lp;
        }
    }
    __syncthreads();

    for (int t = 0; t < T_; ++t) {
        const int s = seq[t];

        sb1[tid] = b1[s * NL_ + tid];
        if (tid < NO_) { sb2[tid] = b2[s * NO_ + tid]; sidx[tid] = out_idx[s * NO_ + tid]; }
        stage_w2(s0, s, tid);
        CPCOMMIT();
        stage_w1(s0, 0, s, 0, tid);
        CPCOMMIT();

        // -------- Phase 1: D = x @ W1^T over 8 K-chunks (K=32 each) --------
        float acc[8][4];
        #pragma unroll
        for (int nt = 0; nt < 8; ++nt)
            #pragma unroll
            for (int i = 0; i < 4; ++i) acc[nt][i] = 0.f;

        for (int c = 0; c < 8; ++c) {
            if (c < 7) { stage_w1(s0, (c + 1) % 3, s, c + 1, tid); CPCOMMIT(); }
            if (c < 7) asm volatile("cp.async.wait_group 1;" ::: "memory");
            else       asm volatile("cp.async.wait_group 0;" ::: "memory");
            __syncthreads();

            uint32_t wb = s0 + OFF_W1 + (uint32_t)((c % 3) * W1BUF);

            #pragma unroll
            for (int ks = 0; ks < 2; ++ks) {
                int gk = c * 32 + ks * 16;        // global k for x
                int ck = ks * 16;                 // k within chunk for W1
                uint32_t ah[4], al[4];
                ldm4(s0 + OFF_XH + (uint32_t)((mrow + a_row) * XPB + (gk + a_kof) * 2),
                     ah[0], ah[1], ah[2], ah[3]);
                ldm4(s0 + OFF_XL + (uint32_t)((mrow + a_row) * XPB + (gk + a_kof) * 2),
                     al[0], al[1], al[2], al[3]);
                #pragma unroll
                for (int p = 0; p < 4; ++p) {
                    int nbase = ncol0 + p * 16;
                    uint32_t bh0, bh1, bh2, bh3, bl0, bl1, bl2, bl3;
                    uint32_t baddr = wb + (uint32_t)((nbase + b_row) * W1PB + (ck + b_kof) * 2);
                    ldm4(baddr, bh0, bh1, bh2, bh3);
                    ldm4(baddr + W1PLANE, bl0, bl1, bl2, bl3);
                    mma16816(acc[2 * p],     ah, bh0, bh1);
                    mma16816(acc[2 * p],     al, bh0, bh1);
                    mma16816(acc[2 * p],     ah, bl0, bl1);
                    mma16816(acc[2 * p + 1], ah, bh2, bh3);
                    mma16816(acc[2 * p + 1], al, bh2, bh3);
                    mma16816(acc[2 * p + 1], ah, bl2, bl3);
                }
            }
        }
        __syncthreads();   // all x reads done before in-place rewrite

        // -------- Epilogue 1: tanh(acc + b1) -> XH/XL --------
        {
            int rowa = mrow + (lane >> 2);
            int rowb = rowa + 8;
            #pragma unroll
            for (int nt = 0; nt < 8; ++nt) {
                int colb = ncol0 + nt * 8 + 2 * (lane & 3);
                float2 bb = *(const float2*)(sb1 + colb);
                uint32_t hp, lp;
                pack2(tanh_acc(acc[nt][0] + bb.x), tanh_acc(acc[nt][1] + bb.y), hp, lp);
                *(uint32_t*)(smc + OFF_XH + rowa * XPB + colb * 2) = hp;
                *(uint32_t*)(smc + OFF_XL + rowa * XPB + colb * 2) = lp;
                pack2(tanh_acc(acc[nt][2] + bb.x), tanh_acc(acc[nt][3] + bb.y), hp, lp);
                *(uint32_t*)(smc + OFF_XH + rowb * XPB + colb * 2) = hp;
                *(uint32_t*)(smc + OFF_XL + rowb * XPB + colb * 2) = lp;
            }
        }
        __syncthreads();

        // -------- Phase 2: logits = x_new @ W2^T (one m16n8 tile per warp) --------
        {
            float a2[4] = {0.f, 0.f, 0.f, 0.f};
            #pragma unroll
            for (int ks = 0; ks < 16; ++ks) {
                int gk = ks * 16;
                uint32_t ah[4], al[4];
                ldm4(s0 + OFF_XH + (uint32_t)((mrow2 + a_row) * XPB + (gk + a_kof) * 2),
                     ah[0], ah[1], ah[2], ah[3]);
                ldm4(s0 + OFF_XL + (uint32_t)((mrow2 + a_row) * XPB + (gk + a_kof) * 2),
                     al[0], al[1], al[2], al[3]);
                uint32_t baddr = s0 + (uint32_t)(OFF_W2H
                               + (nb2 + (lane & 7)) * XPB + (gk + ((lane >> 3) & 1) * 8) * 2);
                uint32_t bh0, bh1, bl0, bl1;
                ldm2(baddr, bh0, bh1);
                ldm2(baddr + (OFF_W2L - OFF_W2H), bl0, bl1);
                mma16816(a2, ah, bh0, bh1);
                mma16816(a2, al, bh0, bh1);
                mma16816(a2, ah, bl0, bl1);
            }
            int rowa = mrow2 + (lane >> 2);
            int colb = nb2 + 2 * (lane & 3);
            *(float2*)(ylog + rowa * 36 + colb)       = make_float2(a2[0], a2[1]);
            *(float2*)(ylog + (rowa + 8) * 36 + colb) = make_float2(a2[2], a2[3]);
        }
        // zero scatter buffer while logits settle
        for (int i = tid; i < ROWS_ * 68; i += NTH_) yb[i] = 0.f;
        __syncthreads();

        // -------- softmax + last-wins scatter: warp 0, one row per lane --------
        if (w == 0) {
            int r = lane;
            float lg[32];
            float m = -1e30f;
            #pragma unroll
            for (int o = 0; o < 32; ++o) {
                lg[o] = ylog[r * 36 + o] + sb2[o];
                m = fmaxf(m, lg[o]);
            }
            float ssum = 0.f;
            #pragma unroll
            for (int o = 0; o < 32; ++o) { lg[o] = __expf(lg[o] - m); ssum += lg[o]; }
            float inv = __frcp_rn(ssum);
            float* yrow = yb + r * 68;
            #pragma unroll
            for (int o = 0; o < 32; ++o)
                yrow[sidx[o]] = lg[o] * inv;          // ascending o -> last wins
        }
        __syncthreads();

        // -------- coalesced copy-out: 32 rows x 64 floats --------
        #pragma unroll
        for (int q = 0; q < 2; ++q) {
            int g = tid + NTH_ * q;       // 0..511 float4s
            int row = g >> 4, f4 = g & 15;
            float4 o4 = *(const float4*)(yb + row * 68 + f4 * 4);
            *(float4*)(out + ((size_t)(r0 + row) * T_ + t) * V_ + f4 * 4) = o4;
        }
        __syncthreads();
    }
}

extern "C" void kernel_launch(void* const* d_in, const int* in_sizes, int n_in,
                              void* d_out, int out_size)
{
    const float* latent0   = (const float*)d_in[0];
    const float* W1        = (const float*)d_in[1];
    const float* b1        = (const float*)d_in[2];
    const float* W2        = (const float*)d_in[3];
    const float* b2        = (const float*)d_in[4];
    const int*   state_seq = (const int*)  d_in[5];
    const int*   out_idx   = (const int*)  d_in[6];
    float*       out       = (float*)      d_out;

    cvt_kernel<<<(int)(((size_t)NS_ * NL_ * NL_ + 255) / 256), 256>>>(W1, W2);

    cudaFuncSetAttribute(lalr_hmma_kernel,
                         cudaFuncAttributeMaxDynamicSharedMemorySize, SMEM_TOTAL);
    lalr_hmma_kernel<<<GRID_, NTH_, SMEM_TOTAL>>>(latent0, b1, b2, state_seq, out_idx, out);
}

// round 9
// speedup vs baseline: 2.8429x; 1.2894x over previous
#include <cuda_runtime.h>
#include <cuda_bf16.h>
#include <cstdint>
#include <cstddef>

#define B_    4096
#define T_    128
#define NL_   256
#define NS_   64
#define NO_   32
#define V_    64
#define ROWS_ 32
#define GRID_ 128
#define NTH_  256

// smem byte offsets
#define OFF_SEQ   0          // 128 ints
#define OFF_SB1   512        // 256 f32
#define OFF_SB2   1536       // 32 f32
#define OFF_SIDX  1664       // 32 int
#define OFF_YLOG  1792       // 32*36 f32 = 4608
#define OFF_YB    6400       // 32*68 f32 = 8704 -> 15104
#define OFF_XH    15104      // 32*528
#define OFF_XL    32000
#define OFF_W2H   48896      // 32*528
#define OFF_W2L   65792
#define OFF_W1    82688      // 8 warps * 2 bufs * 5120
#define SMEM_TOTAL 164608

#define XPB    528           // x / W2 plane pitch (bytes)
#define W1PB   80            // W1 row pitch (bytes)
#define W1PLANE 2560         // 32 rows * 80
#define W1BUF   5120         // hi+lo planes
#define W1WARP  10240        // 2 buffers

__device__ __nv_bfloat16 g_W1h[(size_t)NS_ * NL_ * NL_];
__device__ __nv_bfloat16 g_W1l[(size_t)NS_ * NL_ * NL_];
__device__ __nv_bfloat16 g_W2h[(size_t)NS_ * NO_ * NL_];
__device__ __nv_bfloat16 g_W2l[(size_t)NS_ * NO_ * NL_];

__device__ __forceinline__ void cp16g(uint32_t dst, const void* src) {
    asm volatile("cp.async.cg.shared.global [%0], [%1], 16;" :: "r"(dst), "l"(src) : "memory");
}
#define CPCOMMIT() asm volatile("cp.async.commit_group;" ::: "memory")
#define CPWAIT0()  asm volatile("cp.async.wait_group 0;" ::: "memory")
#define CPWAIT1()  asm volatile("cp.async.wait_group 1;" ::: "memory")
#define CPWAIT2()  asm volatile("cp.async.wait_group 2;" ::: "memory")

__device__ __forceinline__ void ldm4(uint32_t a, uint32_t* r) {
    asm volatile("ldmatrix.sync.aligned.m8n8.x4.shared.b16 {%0,%1,%2,%3}, [%4];"
                 : "=r"(r[0]), "=r"(r[1]), "=r"(r[2]), "=r"(r[3]) : "r"(a));
}
__device__ __forceinline__ void ldm2(uint32_t a, uint32_t& r0, uint32_t& r1) {
    asm volatile("ldmatrix.sync.aligned.m8n8.x2.shared.b16 {%0,%1}, [%2];"
                 : "=r"(r0), "=r"(r1) : "r"(a));
}
__device__ __forceinline__ void mma16816(float* d, const uint32_t* a, uint32_t b0, uint32_t b1) {
    asm volatile("mma.sync.aligned.m16n8k16.row.col.f32.bf16.bf16.f32 "
                 "{%0,%1,%2,%3}, {%4,%5,%6,%7}, {%8,%9}, {%0,%1,%2,%3};"
                 : "+f"(d[0]), "+f"(d[1]), "+f"(d[2]), "+f"(d[3])
                 : "r"(a[0]), "r"(a[1]), "r"(a[2]), "r"(a[3]), "r"(b0), "r"(b1));
}
__device__ __forceinline__ float tanh_acc(float x) {
    float xc = fminf(fmaxf(x, -15.f), 15.f);
    float e = __expf(2.f * xc);
    return __fdividef(e - 1.f, e + 1.f);
}
__device__ __forceinline__ void pack2(float f0, float f1, uint32_t& hp, uint32_t& lp) {
    asm("cvt.rn.bf16x2.f32 %0, %1, %2;" : "=r"(hp) : "f"(f1), "f"(f0));
    float h0 = __uint_as_float(hp << 16);
    float h1 = __uint_as_float(hp & 0xffff0000u);
    asm("cvt.rn.bf16x2.f32 %0, %1, %2;" : "=r"(lp) : "f"(f1 - h1), "f"(f0 - h0));
}

// Per-warp W1 slice stage: warp w stages its 32 n-rows x 32 k (hi+lo) of chunk ck.
__device__ __forceinline__ void stage_w1_warp(uint32_t s0, int w, int buf, int s, int ck, int lane) {
    uint32_t base = s0 + OFF_W1 + (uint32_t)(w * W1WARP + buf * W1BUF);
    #pragma unroll
    for (int q = 0; q < 8; ++q) {
        int idx = q * 32 + lane;          // 0..255
        int pl = idx >> 7;
        int rem = idx & 127;
        int n = rem >> 2, slot = rem & 3;
        uint32_t d = base + (uint32_t)(pl * W1PLANE + n * W1PB + slot * 16);
        const __nv_bfloat16* p = (pl ? g_W1l : g_W1h)
                               + (size_t)(s * NL_ + w * 32 + n) * NL_ + ck * 32 + slot * 8;
        cp16g(d, p);
    }
    CPCOMMIT();
}
// Stage W2[s] hi+lo (CTA-wide, 2048 cp16).
__device__ __forceinline__ void stage_w2(uint32_t s0, int s, int tid) {
    #pragma unroll
    for (int q = 0; q < 8; ++q) {
        int g = tid + NTH_ * q;
        int pl = g >> 10;
        int rem = g & 1023;
        int n = rem >> 5, slot = rem & 31;
        uint32_t d = s0 + (uint32_t)((pl ? OFF_W2L : OFF_W2H) + n * XPB + slot * 16);
        const __nv_bfloat16* p = (pl ? g_W2l : g_W2h) + (size_t)(s * NO_ + n) * NL_ + slot * 8;
        cp16g(d, p);
    }
    CPCOMMIT();
}

__global__ void cvt_kernel(const float* __restrict__ W1, const float* __restrict__ W2) {
    size_t i = (size_t)blockIdx.x * blockDim.x + threadIdx.x;
    if (i < (size_t)NS_ * NL_ * NL_) {
        float x = W1[i];
        __nv_bfloat16 h = __float2bfloat16(x);
        g_W1h[i] = h;
        g_W1l[i] = __float2bfloat16(x - __bfloat162float(h));
    }
    if (i < (size_t)NS_ * NO_ * NL_) {
        float x = W2[i];
        __nv_bfloat16 h = __float2bfloat16(x);
        g_W2h[i] = h;
        g_W2l[i] = __float2bfloat16(x - __bfloat162float(h));
    }
}

__global__ __launch_bounds__(NTH_, 1)
void lalr_hmma_kernel(const float* __restrict__ latent0,
                      const float* __restrict__ b1,
                      const float* __restrict__ b2,
                      const int*   __restrict__ state_seq,
                      const int*   __restrict__ out_idx,
                      float*       __restrict__ out)
{
    extern __shared__ char smc[];
    const uint32_t s0 = (uint32_t)__cvta_generic_to_shared(smc);
    const int tid  = threadIdx.x;
    const int w    = tid >> 5;
    const int lane = tid & 31;
    const int r0   = blockIdx.x * ROWS_;

    int*   seq  = (int*)(smc + OFF_SEQ);
    float* sb1  = (float*)(smc + OFF_SB1);
    float* sb2  = (float*)(smc + OFF_SB2);
    int*   sidx = (int*)(smc + OFF_SIDX);
    float* ylog = (float*)(smc + OFF_YLOG);   // pitch 36 floats
    float* yb   = (float*)(smc + OFF_YB);     // pitch 68 floats

    // phase-1: warp owns m32 x n32 (n-group = w*32); phase-2: m16n8 tile per warp
    const int wn    = w * 32;
    const int mrow2 = (w & 1) * 16;
    const int nb2   = (w >> 1) * 8;

    const int a_row = (lane & 7) + ((lane >> 3) & 1) * 8;
    const int a_kof = (lane >> 4) * 8;
    const int b_row = (lane & 7) + ((lane >> 4) & 1) * 8;
    const int b_kof = ((lane >> 3) & 1) * 8;

    if (tid < T_) seq[tid] = state_seq[tid];

    // initial latent -> XH/XL (bf16 hi/lo planes)
    {
        int r = tid >> 3;
        int cb = (tid & 7) * 32;
        const float2* src = (const float2*)(latent0 + (size_t)(r0 + r) * NL_ + cb);
        #pragma unroll
        for (int i = 0; i < 16; ++i) {
            float2 f = src[i];
            uint32_t hp, lp;
            pack2(f.x, f.y, hp, lp);
            *(uint32_t*)(smc + OFF_XH + r * XPB + (cb + 2 * i) * 2) = hp;
            *(uint32_t*)(smc + OFF_XL + r * XPB + (cb + 2 * i) * 2) = lp;
        }
    }
    // prologue: stage chunks 0,1 of step 0 into this warp's ring
    {
        int sfirst = state_seq[0];
        stage_w1_warp(s0, w, 0, sfirst, 0, lane);
        stage_w1_warp(s0, w, 1, sfirst, 1, lane);
    }
    __syncthreads();

    for (int t = 0; t < T_; ++t) {
        const int s = seq[t];

        sb1[tid] = b1[s * NL_ + tid];
        if (tid < NO_) { sb2[tid] = b2[s * NO_ + tid]; sidx[tid] = out_idx[s * NO_ + tid]; }
        stage_w2(s0, s, tid);

        // -------- Phase 1: x @ W1^T, per-warp ring, no CTA barriers --------
        float acc[2][4][4];
        #pragma unroll
        for (int mt = 0; mt < 2; ++mt)
            #pragma unroll
            for (int q = 0; q < 4; ++q)
                #pragma unroll
                for (int i = 0; i < 4; ++i) acc[mt][q][i] = 0.f;

        const uint32_t wbase = s0 + OFF_W1 + (uint32_t)(w * W1WARP);

        #pragma unroll
        for (int c = 0; c < 8; ++c) {
            if (c < 2)      CPWAIT2();
            else if (c < 7) CPWAIT1();
            else            CPWAIT0();
            __syncwarp();

            const uint32_t wb = wbase + (uint32_t)((c & 1) * W1BUF);

            #pragma unroll
            for (int ks = 0; ks < 2; ++ks) {
                int gk = c * 32 + ks * 16;
                int ck2 = ks * 16;
                uint32_t ah[2][4], al[2][4];
                ldm4(s0 + OFF_XH + (uint32_t)(a_row * XPB + (gk + a_kof) * 2), ah[0]);
                ldm4(s0 + OFF_XH + (uint32_t)((16 + a_row) * XPB + (gk + a_kof) * 2), ah[1]);
                ldm4(s0 + OFF_XL + (uint32_t)(a_row * XPB + (gk + a_kof) * 2), al[0]);
                ldm4(s0 + OFF_XL + (uint32_t)((16 + a_row) * XPB + (gk + a_kof) * 2), al[1]);
                #pragma unroll
                for (int p = 0; p < 2; ++p) {
                    uint32_t bh[4], bl[4];
                    uint32_t baddr = wb + (uint32_t)((p * 16 + b_row) * W1PB + (ck2 + b_kof) * 2);
                    ldm4(baddr, bh);
                    ldm4(baddr + W1PLANE, bl);
                    #pragma unroll
                    for (int mt = 0; mt < 2; ++mt) {
                        mma16816(acc[mt][2 * p],     ah[mt], bh[0], bh[1]);
                        mma16816(acc[mt][2 * p],     al[mt], bh[0], bh[1]);
                        mma16816(acc[mt][2 * p],     ah[mt], bl[0], bl[1]);
                        mma16816(acc[mt][2 * p + 1], ah[mt], bh[2], bh[3]);
                        mma16816(acc[mt][2 * p + 1], al[mt], bh[2], bh[3]);
                        mma16816(acc[mt][2 * p + 1], ah[mt], bl[2], bl[3]);
                    }
                }
            }

            if (c < 6) {
                stage_w1_warp(s0, w, c & 1, s, c + 2, lane);
            } else if (c == 7) {
                int sn = (t < T_ - 1) ? seq[t + 1] : s;
                stage_w1_warp(s0, w, 0, sn, 0, lane);
                stage_w1_warp(s0, w, 1, sn, 1, lane);
            }
        }
        __syncthreads();   // BAR_A: all phase-1 x reads done (also publishes W2 stage)

        // -------- Epilogue 1: tanh(acc + b1) -> XH/XL (warp's own n-columns) ------
        {
            int rowa = lane >> 2;
            #pragma unroll
            for (int mt = 0; mt < 2; ++mt) {
                #pragma unroll
                for (int q = 0; q < 4; ++q) {
                    int colb = wn + q * 8 + 2 * (lane & 3);
                    float2 bb = *(const float2*)(sb1 + colb);
                    int ra = mt * 16 + rowa;
                    uint32_t hp, lp;
                    pack2(tanh_acc(acc[mt][q][0] + bb.x), tanh_acc(acc[mt][q][1] + bb.y), hp, lp);
                    *(uint32_t*)(smc + OFF_XH + ra * XPB + colb * 2) = hp;
                    *(uint32_t*)(smc + OFF_XL + ra * XPB + colb * 2) = lp;
                    pack2(tanh_acc(acc[mt][q][2] + bb.x), tanh_acc(acc[mt][q][3] + bb.y), hp, lp);
                    *(uint32_t*)(smc + OFF_XH + (ra + 8) * XPB + colb * 2) = hp;
                    *(uint32_t*)(smc + OFF_XL + (ra + 8) * XPB + colb * 2) = lp;
                }
            }
        }
        __syncthreads();   // BAR_B: x_new complete before phase-2 reads

        // -------- Phase 2: logits = x_new @ W2^T (m16n8 per warp) --------
        {
            float a2[4] = {0.f, 0.f, 0.f, 0.f};
            #pragma unroll
            for (int ks = 0; ks < 16; ++ks) {
                int gk = ks * 16;
                uint32_t ah[4], al[4];
                ldm4(s0 + OFF_XH + (uint32_t)((mrow2 + a_row) * XPB + (gk + a_kof) * 2), ah);
                ldm4(s0 + OFF_XL + (uint32_t)((mrow2 + a_row) * XPB + (gk + a_kof) * 2), al);
                uint32_t baddr = s0 + (uint32_t)(OFF_W2H
                               + (nb2 + (lane & 7)) * XPB + (gk + ((lane >> 3) & 1) * 8) * 2);
                uint32_t bh0, bh1, bl0, bl1;
                ldm2(baddr, bh0, bh1);
                ldm2(baddr + (OFF_W2L - OFF_W2H), bl0, bl1);
                mma16816(a2, ah, bh0, bh1);
                mma16816(a2, al, bh0, bh1);
                mma16816(a2, ah, bl0, bl1);
            }
            int rowa = mrow2 + (lane >> 2);
            int colb = nb2 + 2 * (lane & 3);
            *(float2*)(ylog + rowa * 36 + colb)       = make_float2(a2[0], a2[1]);
            *(float2*)(ylog + (rowa + 8) * 36 + colb) = make_float2(a2[2], a2[3]);
        }
        __syncthreads();   // BAR_C: logits visible

        // -------- Output path: 4 lanes/warp, each privately owns one row --------
        if (lane < 4) {
            int r = w * 4 + lane;
            float lg[32];
            float m = -1e30f;
            #pragma unroll
            for (int o = 0; o < 32; ++o) {
                lg[o] = ylog[r * 36 + o] + sb2[o];
                m = fmaxf(m, lg[o]);
            }
            float ssum = 0.f;
            #pragma unroll
            for (int o = 0; o < 32; ++o) { lg[o] = __expf(lg[o] - m); ssum += lg[o]; }
            float inv = __frcp_rn(ssum);
            float* yrow = yb + r * 68;
            #pragma unroll
            for (int q4 = 0; q4 < 16; ++q4)
                *(float4*)(yrow + 4 * q4) = make_float4(0.f, 0.f, 0.f, 0.f);
            #pragma unroll
            for (int o = 0; o < 32; ++o)
                yrow[sidx[o]] = lg[o] * inv;          // ascending o -> last wins
            float* orow = out + ((size_t)(r0 + r) * T_ + t) * V_;
            #pragma unroll
            for (int q4 = 0; q4 < 16; ++q4)
                *(float4*)(orow + 4 * q4) = *(const float4*)(yrow + 4 * q4);
        }
        // no barrier: yb/out rows are lane-private; ylog rewritten only after next BAR_B
    }
}

extern "C" void kernel_launch(void* const* d_in, const int* in_sizes, int n_in,
                              void* d_out, int out_size)
{
    const float* latent0   = (const float*)d_in[0];
    const float* W1        = (const float*)d_in[1];
    const float* b1        = (const float*)d_in[2];
    const float* W2        = (const float*)d_in[3];
    const float* b2        = (const float*)d_in[4];
    const int*   state_seq = (const int*)  d_in[5];
    const int*   out_idx   = (const int*)  d_in[6];
    float*       out       = (float*)      d_out;

    cvt_kernel<<<(int)(((size_t)NS_ * NL_ * NL_ + 255) / 256), 256>>>(W1, W2);

    cudaFuncSetAttribute(lalr_hmma_kernel,
                         cudaFuncAttributeMaxDynamicSharedMemorySize, SMEM_TOTAL);
    lalr_hmma_kernel<<<GRID_, NTH_, SMEM_TOTAL>>>(latent0, b1, b2, state_seq, out_idx, out);
}